// round 14
// baseline (speedup 1.0000x reference)
#include <cuda_runtime.h>
#include <math.h>

#define NN 50000
#define EE 600000
#define HH 8
#define HD 128
#define CAP 64

// ---------------- scratch (static device globals; no allocation) ------------
__device__ float g_feat[NN * HD];
__device__ float g_el[NN * HH];
__device__ float g_er[NN * HH];
__device__ float g_sumw[NN * HH];
__device__ float g_ssum[HD];
__device__ float g_ssq[HD];
__device__ int g_cnt[NN];
__device__ int g_off[NN];
__device__ int g_cur[NN];
__device__ int g_eid[EE];
__device__ int g_esrc[EE];
__device__ int g_bsum2[64];

static cudaStream_t g_s2;
static cudaEvent_t g_ev0, g_ev1;
struct _StreamInit {
    _StreamInit() {
        cudaStreamCreateWithFlags(&g_s2, cudaStreamNonBlocking);
        cudaEventCreateWithFlags(&g_ev0, cudaEventDisableTiming);
        cudaEventCreateWithFlags(&g_ev1, cudaEventDisableTiming);
    }
};
static _StreamInit _stream_init;

__device__ __forceinline__ void red_add_v4(float* p, float a, float b, float c, float d) {
    asm volatile("red.global.add.v4.f32 [%0], {%1,%2,%3,%4};"
                 :: "l"(__cvta_generic_to_global(p)),
                    "f"(a), "f"(b), "f"(c), "f"(d) : "memory");
}

#define MMA_TF32(C, a0, a1, a2, a3, b0, b1)                                   \
    asm volatile("mma.sync.aligned.m16n8k8.row.col.f32.tf32.tf32.f32 "        \
                 "{%0,%1,%2,%3}, {%4,%5,%6,%7}, {%8,%9}, {%0,%1,%2,%3};"      \
                 : "+f"(C[0]), "+f"(C[1]), "+f"(C[2]), "+f"(C[3])             \
                 : "r"(a0), "r"(a1), "r"(a2), "r"(a3), "r"(b0), "r"(b1))

__device__ __forceinline__ unsigned tf32_hi(float x) {
    unsigned h; asm("cvt.rna.tf32.f32 %0, %1;" : "=r"(h) : "f"(x)); return h;
}

// ---------------- K0: init ---------------------------------------------------
__global__ void k_init(float* __restrict__ out) {
    int stride = gridDim.x * blockDim.x;
    int i0 = blockIdx.x * blockDim.x + threadIdx.x;
    for (int i = i0; i < NN * HH; i += stride) g_sumw[i] = 0.0f;
    for (int i = i0; i < NN; i += stride) g_cnt[i] = 0;
    for (int i = i0; i < 512; i += stride)
        out[(size_t)NN * HD + (size_t)EE * HH + i] = 0.0f;
    for (int i = i0; i < HD; i += stride) { g_ssum[i] = 0.0f; g_ssq[i] = 0.0f; }
}

// ---------------- K1: 3xTF32 tensor-core GEMM + fused el/er epilogue ---------
// feat[bm..bm+127][0..127] = A[rows][128] @ W[128][128]^T
__global__ __launch_bounds__(256) void k_gemm_tc(
    const float* __restrict__ A, const float* __restrict__ W,
    const float* __restrict__ al, const float* __restrict__ ar) {
    __shared__ float As_hi[128][20], As_lo[128][20];
    __shared__ float Ws_hi[128][20], Ws_lo[128][20];
    __shared__ float s_al[128], s_ar[128];
    int tid = threadIdx.x, lane = tid & 31, wid = tid >> 5;
    int bm = blockIdx.x * 128;
    if (tid < 128) { s_al[tid] = al[tid]; s_ar[tid] = ar[tid]; }

    float c[16][4];
#pragma unroll
    for (int i = 0; i < 16; i++)
#pragma unroll
        for (int j = 0; j < 4; j++) c[i][j] = 0.0f;

    int arow = lane >> 2, acol = lane & 3;     // fragment row-group / in-group id
    int srow = tid >> 1, scol = (tid & 1) * 8; // staging coords

    for (int kc = 0; kc < 128; kc += 16) {
        // stage A (rows may exceed NN) and W, split into tf32 hi/lo
#pragma unroll
        for (int q = 0; q < 8; q += 4) {
            float4 v = make_float4(0.f, 0.f, 0.f, 0.f);
            if (bm + srow < NN)
                v = *(const float4*)(A + (size_t)(bm + srow) * 128 + kc + scol + q);
            float xs[4] = {v.x, v.y, v.z, v.w};
#pragma unroll
            for (int d = 0; d < 4; d++) {
                float hf = __uint_as_float(tf32_hi(xs[d]));
                As_hi[srow][scol + q + d] = hf;
                As_lo[srow][scol + q + d] = xs[d] - hf;
            }
            float4 wv = *(const float4*)(W + (size_t)srow * 128 + kc + scol + q);
            float ws[4] = {wv.x, wv.y, wv.z, wv.w};
#pragma unroll
            for (int d = 0; d < 4; d++) {
                float hf = __uint_as_float(tf32_hi(ws[d]));
                Ws_hi[srow][scol + q + d] = hf;
                Ws_lo[srow][scol + q + d] = ws[d] - hf;
            }
        }
        __syncthreads();
#pragma unroll
        for (int ks = 0; ks < 2; ks++) {
            int kk = ks * 8;
            int am = wid * 16 + arow;
            unsigned ah0 = __float_as_uint(As_hi[am][kk + acol]);
            unsigned ah1 = __float_as_uint(As_hi[am + 8][kk + acol]);
            unsigned ah2 = __float_as_uint(As_hi[am][kk + acol + 4]);
            unsigned ah3 = __float_as_uint(As_hi[am + 8][kk + acol + 4]);
            unsigned av0 = __float_as_uint(As_lo[am][kk + acol]);
            unsigned av1 = __float_as_uint(As_lo[am + 8][kk + acol]);
            unsigned av2 = __float_as_uint(As_lo[am][kk + acol + 4]);
            unsigned av3 = __float_as_uint(As_lo[am + 8][kk + acol + 4]);
#pragma unroll
            for (int n0 = 0; n0 < 16; n0++) {
                int bn = n0 * 8 + arow;
                unsigned bh0 = __float_as_uint(Ws_hi[bn][kk + acol]);
                unsigned bh1 = __float_as_uint(Ws_hi[bn][kk + acol + 4]);
                unsigned bl0 = __float_as_uint(Ws_lo[bn][kk + acol]);
                unsigned bl1 = __float_as_uint(Ws_lo[bn][kk + acol + 4]);
                MMA_TF32(c[n0], ah0, ah1, ah2, ah3, bh0, bh1);
                MMA_TF32(c[n0], ah0, ah1, ah2, ah3, bl0, bl1);
                MMA_TF32(c[n0], av0, av1, av2, av3, bh0, bh1);
            }
        }
        __syncthreads();
    }

    // epilogue: store feat + accumulate el/er partials
    int r0 = bm + wid * 16 + arow;
    int r1 = r0 + 8;
    float pel0[8], per0[8], pel1[8], per1[8];
#pragma unroll
    for (int hh = 0; hh < 8; hh++) { pel0[hh] = per0[hh] = pel1[hh] = per1[hh] = 0.f; }
#pragma unroll
    for (int n0 = 0; n0 < 16; n0++) {
        int cb = n0 * 8 + 2 * acol;
        int hh = n0 >> 1;
        float a0v = s_al[cb], a1v = s_al[cb + 1];
        float b0v = s_ar[cb], b1v = s_ar[cb + 1];
        if (r0 < NN) *(float2*)(g_feat + (size_t)r0 * 128 + cb) = make_float2(c[n0][0], c[n0][1]);
        if (r1 < NN) *(float2*)(g_feat + (size_t)r1 * 128 + cb) = make_float2(c[n0][2], c[n0][3]);
        pel0[hh] += c[n0][0] * a0v + c[n0][1] * a1v;
        per0[hh] += c[n0][0] * b0v + c[n0][1] * b1v;
        pel1[hh] += c[n0][2] * a0v + c[n0][3] * a1v;
        per1[hh] += c[n0][2] * b0v + c[n0][3] * b1v;
    }
#pragma unroll
    for (int hh = 0; hh < 8; hh++) {
        pel0[hh] += __shfl_xor_sync(0xFFFFFFFF, pel0[hh], 1);
        pel0[hh] += __shfl_xor_sync(0xFFFFFFFF, pel0[hh], 2);
        per0[hh] += __shfl_xor_sync(0xFFFFFFFF, per0[hh], 1);
        per0[hh] += __shfl_xor_sync(0xFFFFFFFF, per0[hh], 2);
        pel1[hh] += __shfl_xor_sync(0xFFFFFFFF, pel1[hh], 1);
        pel1[hh] += __shfl_xor_sync(0xFFFFFFFF, pel1[hh], 2);
        per1[hh] += __shfl_xor_sync(0xFFFFFFFF, per1[hh], 1);
        per1[hh] += __shfl_xor_sync(0xFFFFFFFF, per1[hh], 2);
    }
    if (acol == 0) {
        if (r0 < NN) {
#pragma unroll
            for (int hh = 0; hh < 8; hh++) {
                g_el[(size_t)r0 * 8 + hh] = pel0[hh];
                g_er[(size_t)r0 * 8 + hh] = per0[hh];
            }
        }
        if (r1 < NN) {
#pragma unroll
            for (int hh = 0; hh < 8; hh++) {
                g_el[(size_t)r1 * 8 + hh] = pel1[hh];
                g_er[(size_t)r1 * 8 + hh] = per1[hh];
            }
        }
    }
}

// ---------------- CSR build --------------------------------------------------
__global__ void k_csr_count(const int* __restrict__ dst) {
    int i = blockIdx.x * blockDim.x + threadIdx.x;
    if (i < EE) atomicAdd(&g_cnt[dst[i]], 1);
}

__global__ __launch_bounds__(1024) void k_scanA() {
    __shared__ int sh[1024];
    int t = threadIdx.x, idx = blockIdx.x * 1024 + t;
    int v = (idx < NN) ? g_cnt[idx] : 0;
    sh[t] = v;
    __syncthreads();
    for (int off = 1; off < 1024; off <<= 1) {
        int u = (t >= off) ? sh[t - off] : 0;
        __syncthreads();
        sh[t] += u;
        __syncthreads();
    }
    if (idx < NN) g_off[idx] = sh[t] - v;
    if (t == 1023) g_bsum2[blockIdx.x] = sh[t];
}

__global__ void k_scanB() {
    __shared__ int sh[64];
    int t = threadIdx.x;
    int v = (t < 49) ? g_bsum2[t] : 0;
    sh[t] = v;
    __syncthreads();
    for (int off = 1; off < 64; off <<= 1) {
        int u = (t >= off) ? sh[t - off] : 0;
        __syncthreads();
        sh[t] += u;
        __syncthreads();
    }
    g_bsum2[t] = sh[t] - v;
}

__global__ __launch_bounds__(1024) void k_scanC() {
    int idx = blockIdx.x * 1024 + threadIdx.x;
    if (idx < NN) {
        int o = g_off[idx] + g_bsum2[blockIdx.x];
        g_off[idx] = o;
        g_cur[idx] = o;
    }
}

__global__ void k_fill(const int* __restrict__ src, const int* __restrict__ dst) {
    int i = blockIdx.x * blockDim.x + threadIdx.x;
    if (i >= EE) return;
    int d = dst[i];
    int pos = atomicAdd(&g_cur[d], 1);
    g_eid[pos] = i;
    g_esrc[pos] = src[i];
}

// ---------------- K5: fused softmax + attn + edge-MLP + message gather -------
// one warp per node (R11 structure: raw exp in s_a, invz folded into P3)
__global__ __launch_bounds__(256) void k_node_all(
    const float* __restrict__ aw1, const float* __restrict__ ab1,
    const float* __restrict__ aw2, const float* __restrict__ ab2,
    float* __restrict__ attn, float* __restrict__ hout) {
    __shared__ float s_aw1[64], s_aw2[64], s_ab1[8], s_ab2[8];
    __shared__ int   s_src[8][CAP];
    __shared__ int   s_eid[8][CAP];
    __shared__ float s_a[8][CAP][8];
    __shared__ float s_zi[8][8];
    int tid = threadIdx.x;
    if (tid < 64) { s_aw1[tid] = aw1[tid]; s_aw2[tid] = aw2[tid]; }
    if (tid < 8)  { s_ab1[tid] = ab1[tid]; s_ab2[tid] = ab2[tid]; }
    __syncthreads();
    int w = tid >> 5, lane = tid & 31;
    int n = blockIdx.x * 8 + w;
    if (n >= NN) return;
    int off = g_off[n], deg = g_cnt[n];

    for (int k = lane; k < deg && k < CAP; k += 32) {
        s_src[w][k] = g_esrc[off + k];
        s_eid[w][k] = g_eid[off + k];
    }
    __syncwarp();

    int j = lane >> 3, h = lane & 7, base = lane & 24;
    int quad = lane & ~3;
    float er_h = g_er[(size_t)n * 8 + h];
    float invz;

    if (deg <= CAP) {
        float z = 0.f;
        int k = j;
        for (; k + 12 < deg; k += 16) {
            int s0 = s_src[w][k],      s1 = s_src[w][k + 4];
            int s2 = s_src[w][k + 8],  s3 = s_src[w][k + 12];
            float e0 = g_el[(size_t)s0 * 8 + h] + er_h;
            float e1 = g_el[(size_t)s1 * 8 + h] + er_h;
            float e2 = g_el[(size_t)s2 * 8 + h] + er_h;
            float e3 = g_el[(size_t)s3 * 8 + h] + er_h;
            e0 = (e0 > 0.f) ? e0 : 0.2f * e0;
            e1 = (e1 > 0.f) ? e1 : 0.2f * e1;
            e2 = (e2 > 0.f) ? e2 : 0.2f * e2;
            e3 = (e3 > 0.f) ? e3 : 0.2f * e3;
            float x0 = __expf(e0), x1 = __expf(e1), x2 = __expf(e2), x3 = __expf(e3);
            s_a[w][k][h] = x0;      s_a[w][k + 4][h] = x1;
            s_a[w][k + 8][h] = x2;  s_a[w][k + 12][h] = x3;
            z += (x0 + x1) + (x2 + x3);
        }
        for (; k < deg; k += 4) {
            int s = s_src[w][k];
            float e = g_el[(size_t)s * 8 + h] + er_h;
            e = (e > 0.f) ? e : 0.2f * e;
            float ex = __expf(e);
            s_a[w][k][h] = ex;
            z += ex;
        }
        z += __shfl_xor_sync(0xFFFFFFFF, z, 8);
        z += __shfl_xor_sync(0xFFFFFFFF, z, 16);
        invz = 1.0f / z;
        if (lane < 8) s_zi[w][lane] = invz;
        __syncwarp();

        float vd = 0.f;
        for (int kb = 0; kb < deg; kb += 4) {
            int kk2 = kb + j;
            bool act = (kk2 < deg);
            int s = 0;
            float a = 0.f;
            if (act) {
                s = s_src[w][kk2];
                a = s_a[w][kk2][h] * invz;
                attn[(size_t)s_eid[w][kk2] * 8 + h] = a;
            }
            float t = s_ab1[h];
#pragma unroll
            for (int kk = 0; kk < 8; kk++)
                t = fmaf(__shfl_sync(0xFFFFFFFF, a, base + kk), s_aw1[h * 8 + kk], t);
            float hid = fmaxf(t, 0.f);
            float t2 = s_ab2[h];
#pragma unroll
            for (int kk = 0; kk < 8; kk++)
                t2 = fmaf(__shfl_sync(0xFFFFFFFF, hid, base + kk), s_aw2[h * 8 + kk], t2);
            float val = 1.0f - t2;
            float v0 = __shfl_sync(0xFFFFFFFF, val, quad + 0);
            float v1 = __shfl_sync(0xFFFFFFFF, val, quad + 1);
            float v2 = __shfl_sync(0xFFFFFFFF, val, quad + 2);
            float v3 = __shfl_sync(0xFFFFFFFF, val, quad + 3);
            if (act) {
                if ((h & 3) == 0)
                    red_add_v4(g_sumw + (size_t)s * 8 + (h & 4), v0, v1, v2, v3);
                vd += val;
            }
        }
        vd += __shfl_xor_sync(0xFFFFFFFF, vd, 8);
        vd += __shfl_xor_sync(0xFFFFFFFF, vd, 16);
        if (lane < 8) atomicAdd(&g_sumw[(size_t)n * 8 + lane], vd);
        __syncwarp();

        int c = lane * 4, hsel = lane >> 2;
        float zi_h = s_zi[w][hsel];
        float a0 = 0.f, a1 = 0.f, a2 = 0.f, a3 = 0.f;
        int kk3 = 0;
        for (; kk3 + 8 <= deg; kk3 += 8) {
            int ss[8]; float av[8];
#pragma unroll
            for (int q = 0; q < 8; q++) {
                ss[q] = s_src[w][kk3 + q];
                av[q] = s_a[w][kk3 + q][hsel] * zi_h;
            }
            float4 ff[8];
#pragma unroll
            for (int q = 0; q < 8; q++)
                ff[q] = *(const float4*)(g_feat + (size_t)ss[q] * 128 + c);
#pragma unroll
            for (int q = 0; q < 8; q++) {
                a0 = fmaf(ff[q].x, av[q], a0); a1 = fmaf(ff[q].y, av[q], a1);
                a2 = fmaf(ff[q].z, av[q], a2); a3 = fmaf(ff[q].w, av[q], a3);
            }
        }
        for (; kk3 < deg; kk3++) {
            int s = s_src[w][kk3];
            float av = s_a[w][kk3][hsel] * zi_h;
            float4 f = *(const float4*)(g_feat + (size_t)s * 128 + c);
            a0 = fmaf(f.x, av, a0); a1 = fmaf(f.y, av, a1);
            a2 = fmaf(f.z, av, a2); a3 = fmaf(f.w, av, a3);
        }
        *(float4*)(hout + (size_t)n * 128 + c) = make_float4(a0, a1, a2, a3);
    } else {
        float z = 0.f;
        for (int k = j; k < deg; k += 4) {
            int s = (k < CAP) ? s_src[w][k] : g_esrc[off + k];
            float e = g_el[(size_t)s * 8 + h] + er_h;
            e = (e > 0.f) ? e : 0.2f * e;
            float ex = __expf(e);
            if (k < CAP) s_a[w][k][h] = ex;
            z += ex;
        }
        z += __shfl_xor_sync(0xFFFFFFFF, z, 8);
        z += __shfl_xor_sync(0xFFFFFFFF, z, 16);
        invz = 1.0f / z;
        if (lane < 8) s_zi[w][lane] = invz;
        __syncwarp();

        float vd = 0.f;
        for (int kb = 0; kb < deg; kb += 4) {
            int k = kb + j;
            bool act = (k < deg);
            int s = 0, eid = 0;
            float a = 0.f;
            if (act) {
                if (k < CAP) {
                    s = s_src[w][k]; eid = s_eid[w][k];
                    a = s_a[w][k][h] * invz;
                } else {
                    s = g_esrc[off + k]; eid = g_eid[off + k];
                    float e = g_el[(size_t)s * 8 + h] + er_h;
                    e = (e > 0.f) ? e : 0.2f * e;
                    a = __expf(e) * invz;
                }
                attn[(size_t)eid * 8 + h] = a;
            }
            float t = s_ab1[h];
#pragma unroll
            for (int kk = 0; kk < 8; kk++)
                t = fmaf(__shfl_sync(0xFFFFFFFF, a, base + kk), s_aw1[h * 8 + kk], t);
            float hid = fmaxf(t, 0.f);
            float t2 = s_ab2[h];
#pragma unroll
            for (int kk = 0; kk < 8; kk++)
                t2 = fmaf(__shfl_sync(0xFFFFFFFF, hid, base + kk), s_aw2[h * 8 + kk], t2);
            float val = 1.0f - t2;
            if (act) {
                atomicAdd(&g_sumw[(size_t)s * 8 + h], val);
                vd += val;
            }
        }
        vd += __shfl_xor_sync(0xFFFFFFFF, vd, 8);
        vd += __shfl_xor_sync(0xFFFFFFFF, vd, 16);
        if (lane < 8) atomicAdd(&g_sumw[(size_t)n * 8 + lane], vd);
        __syncwarp();

        int c = lane * 4, hsel = lane >> 2;
        float zi_h = s_zi[w][hsel];
        float a0 = 0.f, a1 = 0.f, a2 = 0.f, a3 = 0.f;
        for (int k = 0; k < deg; k++) {
            int s; float av;
            if (k < CAP) { s = s_src[w][k]; av = s_a[w][k][hsel] * zi_h; }
            else {
                s = g_esrc[off + k];
                float e = g_el[(size_t)s * 8 + hsel] + g_er[(size_t)n * 8 + hsel];
                e = (e > 0.f) ? e : 0.2f * e;
                av = __expf(e) * zi_h;
            }
            float4 f = *(const float4*)(g_feat + (size_t)s * 128 + c);
            a0 = fmaf(f.x, av, a0); a1 = fmaf(f.y, av, a1);
            a2 = fmaf(f.z, av, a2); a3 = fmaf(f.w, av, a3);
        }
        *(float4*)(hout + (size_t)n * 128 + c) = make_float4(a0, a1, a2, a3);
    }
}

// ---------------- K6: BN statistics only ------------------------------------
__global__ __launch_bounds__(256) void k_node2(
    const float* __restrict__ tw1, const float* __restrict__ tb1,
    const float* __restrict__ tw2, const float* __restrict__ tb2,
    const float* __restrict__ gb, const float* __restrict__ hout) {
    __shared__ float s_tw1[64], s_tb1[8], s_tw2[1024], s_tbg[128];
    __shared__ float s_bsum[128], s_bsq[128];
    int tid = threadIdx.x;
    if (tid < 64) s_tw1[tid] = tw1[tid];
    if (tid < 8)  s_tb1[tid] = tb1[tid];
    for (int j = tid; j < 1024; j += 256) s_tw2[j] = tw2[j];
    if (tid < 128) {
        s_tbg[tid] = tb2[tid] + gb[tid];
        s_bsum[tid] = 0.f; s_bsq[tid] = 0.f;
    }
    __syncthreads();
    int lane = tid & 31, w = tid >> 5;
    int c = lane * 4;
    float lsum[4] = {0, 0, 0, 0}, lsq[4] = {0, 0, 0, 0};
    for (int n = blockIdx.x * 8 + w; n < NN; n += gridDim.x * 8) {
        float4 sw0 = *(const float4*)(g_sumw + (size_t)n * 8);
        float4 sw1 = *(const float4*)(g_sumw + (size_t)n * 8 + 4);
        float swv[8] = {sw0.x, sw0.y, sw0.z, sw0.w, sw1.x, sw1.y, sw1.z, sw1.w};
        float hid[8];
#pragma unroll
        for (int o = 0; o < 8; o++) {
            float t = s_tb1[o];
#pragma unroll
            for (int k = 0; k < 8; k++) t = fmaf(swv[k], s_tw1[o * 8 + k], t);
            hid[o] = fmaxf(t, 0.f);
        }
        float4 acc = *(const float4*)(hout + (size_t)n * 128 + c);
        float av[4] = {acc.x, acc.y, acc.z, acc.w};
#pragma unroll
        for (int j = 0; j < 4; j++) {
            float t = s_tbg[c + j];
#pragma unroll
            for (int k = 0; k < 8; k++) t = fmaf(hid[k], s_tw2[(c + j) * 8 + k], t);
            float ov = av[j] + t;
            lsum[j] += ov;
            lsq[j]  += ov * ov;
        }
    }
#pragma unroll
    for (int j = 0; j < 4; j++) {
        atomicAdd(&s_bsum[c + j], lsum[j]);
        atomicAdd(&s_bsq[c + j], lsq[j]);
    }
    __syncthreads();
    if (tid < 128) {
        atomicAdd(&g_ssum[tid], s_bsum[tid]);
        atomicAdd(&g_ssq[tid], s_bsq[tid]);
    }
}

// ---------------- K7: e_emb recompute + batchnorm + elu + residual -----------
__global__ __launch_bounds__(256) void k_final(
    const float* __restrict__ hin,
    const float* __restrict__ gamma, const float* __restrict__ beta,
    const float* __restrict__ tw1, const float* __restrict__ tb1,
    const float* __restrict__ tw2, const float* __restrict__ tb2,
    const float* __restrict__ gb, float* __restrict__ out) {
    __shared__ float s_tw1[64], s_tb1[8], s_tw2[1024], s_tbg[128];
    __shared__ float s_scale[128], s_shift[128];
    int tid = threadIdx.x;
    if (tid < 64) s_tw1[tid] = tw1[tid];
    if (tid < 8)  s_tb1[tid] = tb1[tid];
    for (int j = tid; j < 1024; j += 256) s_tw2[j] = tw2[j];
    if (tid < 128) {
        s_tbg[tid] = tb2[tid] + gb[tid];
        const float invN = 1.0f / (float)NN;
        float mu = g_ssum[tid] * invN;
        float var = g_ssq[tid] * invN - mu * mu;
        float sc = gamma[tid] * rsqrtf(var + 1e-5f);
        s_scale[tid] = sc;
        s_shift[tid] = beta[tid] - mu * sc;
    }
    __syncthreads();
    int lane = tid & 31, w = tid >> 5;
    int c = lane * 4;
    for (int n = blockIdx.x * 8 + w; n < NN; n += gridDim.x * 8) {
        float4 sw0 = *(const float4*)(g_sumw + (size_t)n * 8);
        float4 sw1 = *(const float4*)(g_sumw + (size_t)n * 8 + 4);
        float swv[8] = {sw0.x, sw0.y, sw0.z, sw0.w, sw1.x, sw1.y, sw1.z, sw1.w};
        float hid[8];
#pragma unroll
        for (int o = 0; o < 8; o++) {
            float t = s_tb1[o];
#pragma unroll
            for (int k = 0; k < 8; k++) t = fmaf(swv[k], s_tw1[o * 8 + k], t);
            hid[o] = fmaxf(t, 0.f);
        }
        float4 acc = *(const float4*)(out + (size_t)n * 128 + c);
        float4 hv  = *(const float4*)(hin + (size_t)n * 128 + c);
        float av[4] = {acc.x, acc.y, acc.z, acc.w};
        float hvv[4] = {hv.x, hv.y, hv.z, hv.w};
        float r[4];
#pragma unroll
        for (int j = 0; j < 4; j++) {
            float t = s_tbg[c + j];
#pragma unroll
            for (int k = 0; k < 8; k++) t = fmaf(hid[k], s_tw2[(c + j) * 8 + k], t);
            float x = av[j] + t;
            float y = x * s_scale[c + j] + s_shift[c + j];
            y = (y > 0.f) ? y : expm1f(y);
            r[j] = hvv[j] + y;
        }
        *(float4*)(out + (size_t)n * 128 + c) = make_float4(r[0], r[1], r[2], r[3]);
    }
}

// ---------------- launcher ----------------------------------------------------
extern "C" void kernel_launch(void* const* d_in, const int* in_sizes, int n_in,
                              void* d_out, int out_size) {
    const float* h        = (const float*)d_in[0];
    const int*   edge_src = (const int*)d_in[1];
    const int*   edge_dst = (const int*)d_in[2];
    const float* fc_w     = (const float*)d_in[4];
    const float* attn_l   = (const float*)d_in[5];
    const float* attn_r   = (const float*)d_in[6];
    const float* gat_bias = (const float*)d_in[7];
    const float* aw1      = (const float*)d_in[8];
    const float* ab1      = (const float*)d_in[9];
    const float* aw2      = (const float*)d_in[10];
    const float* ab2      = (const float*)d_in[11];
    const float* tw1      = (const float*)d_in[12];
    const float* tb1      = (const float*)d_in[13];
    const float* tw2      = (const float*)d_in[14];
    const float* tb2      = (const float*)d_in[15];
    const float* bn_gamma = (const float*)d_in[16];
    const float* bn_beta  = (const float*)d_in[17];

    float* out  = (float*)d_out;
    float* hout = out;                              // [NN*HD]
    float* attn = out + (size_t)NN * HD;            // [EE*HH]

    const int NB = (NN + 1023) / 1024;              // 49

    k_init<<<512, 256>>>(out);
    cudaEventRecord(g_ev0, 0);
    cudaStreamWaitEvent(g_s2, g_ev0, 0);

    k_csr_count<<<(EE + 255) / 256, 256, 0, g_s2>>>(edge_dst);
    k_scanA<<<NB, 1024, 0, g_s2>>>();
    k_scanB<<<1, 64, 0, g_s2>>>();
    k_scanC<<<NB, 1024, 0, g_s2>>>();
    k_fill<<<(EE + 255) / 256, 256, 0, g_s2>>>(edge_src, edge_dst);
    cudaEventRecord(g_ev1, g_s2);

    k_gemm_tc<<<(NN + 127) / 128, 256>>>(h, fc_w, attn_l, attn_r);

    cudaStreamWaitEvent(0, g_ev1, 0);
    k_node_all<<<(NN + 7) / 8, 256>>>(aw1, ab1, aw2, ab2, attn, hout);
    k_node2<<<296, 256>>>(tw1, tb1, tw2, tb2, gat_bias, hout);
    k_final<<<296, 256>>>(h, bn_gamma, bn_beta, tw1, tb1, tw2, tb2, gat_bias, out);
}

// round 15
// speedup vs baseline: 1.0516x; 1.0516x over previous
#include <cuda_runtime.h>
#include <math.h>

#define NN 50000
#define EE 600000
#define HH 8
#define HD 128
#define CAP 64

// ---------------- scratch (static device globals; no allocation) ------------
__device__ float g_feat[NN * HD];
__device__ float g_el[NN * HH];
__device__ float g_er[NN * HH];
__device__ float g_sumw[NN * HH];
__device__ float g_ssum[HD];
__device__ float g_ssq[HD];
__device__ int g_cnt[NN];
__device__ int g_off[NN];
__device__ int g_cur[NN];
__device__ int g_eid[EE];
__device__ int g_esrc[EE];
__device__ int g_bsum2[64];

static cudaStream_t g_s2;
static cudaEvent_t g_ev0, g_ev1;
struct _StreamInit {
    _StreamInit() {
        cudaStreamCreateWithFlags(&g_s2, cudaStreamNonBlocking);
        cudaEventCreateWithFlags(&g_ev0, cudaEventDisableTiming);
        cudaEventCreateWithFlags(&g_ev1, cudaEventDisableTiming);
    }
};
static _StreamInit _stream_init;

__device__ __forceinline__ void red_add_v4(float* p, float a, float b, float c, float d) {
    asm volatile("red.global.add.v4.f32 [%0], {%1,%2,%3,%4};"
                 :: "l"(__cvta_generic_to_global(p)),
                    "f"(a), "f"(b), "f"(c), "f"(d) : "memory");
}

// ---------------- K0: init ---------------------------------------------------
__global__ void k_init(float* __restrict__ out) {
    int stride = gridDim.x * blockDim.x;
    int i0 = blockIdx.x * blockDim.x + threadIdx.x;
    for (int i = i0; i < NN * HH; i += stride) g_sumw[i] = 0.0f;
    for (int i = i0; i < NN; i += stride) g_cnt[i] = 0;
    for (int i = i0; i < 512; i += stride)
        out[(size_t)NN * HD + (size_t)EE * HH + i] = 0.0f;
    for (int i = i0; i < HD; i += stride) { g_ssum[i] = 0.0f; g_ssq[i] = 0.0f; }
}

// ---------------- K1: feat = h @ fc_w.T  + fused el/er epilogue --------------
__global__ __launch_bounds__(256) void k_gemm(const float* __restrict__ A,
                                              const float* __restrict__ W,
                                              const float* __restrict__ al,
                                              const float* __restrict__ ar) {
    __shared__ float As[16][128];
    __shared__ float Bs[16][128];
    __shared__ float s_al[128], s_ar[128];
    const int bm = blockIdx.x * 128;
    const int tid = threadIdx.x;
    const int tm = tid >> 4, tn = tid & 15;
    if (tid < 128) { s_al[tid] = al[tid]; s_ar[tid] = ar[tid]; }

    float acc[8][8];
#pragma unroll
    for (int i = 0; i < 8; i++)
#pragma unroll
        for (int j = 0; j < 8; j++) acc[i][j] = 0.0f;

    for (int k0 = 0; k0 < 128; k0 += 16) {
#pragma unroll
        for (int l = 0; l < 2; l++) {
            int f = tid + l * 256;
            int m = f >> 2;
            int kk = (f & 3) * 4;
            int row = bm + m;
            float4 av = make_float4(0.f, 0.f, 0.f, 0.f);
            if (row < NN) av = *(const float4*)(A + (size_t)row * 128 + k0 + kk);
            As[kk + 0][m] = av.x; As[kk + 1][m] = av.y;
            As[kk + 2][m] = av.z; As[kk + 3][m] = av.w;
            float4 bv = *(const float4*)(W + (size_t)m * 128 + k0 + kk);
            Bs[kk + 0][m] = bv.x; Bs[kk + 1][m] = bv.y;
            Bs[kk + 2][m] = bv.z; Bs[kk + 3][m] = bv.w;
        }
        __syncthreads();
#pragma unroll
        for (int k = 0; k < 16; k++) {
            float a[8], b[8];
            *(float4*)&a[0] = *(const float4*)&As[k][tm * 4];
            *(float4*)&a[4] = *(const float4*)&As[k][64 + tm * 4];
            *(float4*)&b[0] = *(const float4*)&Bs[k][tn * 4];
            *(float4*)&b[4] = *(const float4*)&Bs[k][64 + tn * 4];
#pragma unroll
            for (int i = 0; i < 8; i++)
#pragma unroll
                for (int j = 0; j < 8; j++) acc[i][j] = fmaf(a[i], b[j], acc[i][j]);
        }
        __syncthreads();
    }
#pragma unroll
    for (int i = 0; i < 8; i++) {
        int r = (i < 4) ? (tm * 4 + i) : (64 + tm * 4 + (i - 4));
        int row = bm + r;
        if (row < NN) {
            *(float4*)(g_feat + (size_t)row * 128 + tn * 4) =
                make_float4(acc[i][0], acc[i][1], acc[i][2], acc[i][3]);
            *(float4*)(g_feat + (size_t)row * 128 + 64 + tn * 4) =
                make_float4(acc[i][4], acc[i][5], acc[i][6], acc[i][7]);
        }
        float pel1 = 0.f, per1 = 0.f, pel2 = 0.f, per2 = 0.f;
#pragma unroll
        for (int j = 0; j < 4; j++) {
            pel1 = fmaf(acc[i][j],     s_al[tn * 4 + j],      pel1);
            per1 = fmaf(acc[i][j],     s_ar[tn * 4 + j],      per1);
            pel2 = fmaf(acc[i][j + 4], s_al[64 + tn * 4 + j], pel2);
            per2 = fmaf(acc[i][j + 4], s_ar[64 + tn * 4 + j], per2);
        }
        pel1 += __shfl_xor_sync(0xFFFFFFFF, pel1, 1);
        pel1 += __shfl_xor_sync(0xFFFFFFFF, pel1, 2);
        per1 += __shfl_xor_sync(0xFFFFFFFF, per1, 1);
        per1 += __shfl_xor_sync(0xFFFFFFFF, per1, 2);
        pel2 += __shfl_xor_sync(0xFFFFFFFF, pel2, 1);
        pel2 += __shfl_xor_sync(0xFFFFFFFF, pel2, 2);
        per2 += __shfl_xor_sync(0xFFFFFFFF, per2, 1);
        per2 += __shfl_xor_sync(0xFFFFFFFF, per2, 2);
        if ((tn & 3) == 0 && row < NN) {
            int hh = tn >> 2;
            g_el[(size_t)row * 8 + hh]     = pel1;
            g_el[(size_t)row * 8 + 4 + hh] = pel2;
            g_er[(size_t)row * 8 + hh]     = per1;
            g_er[(size_t)row * 8 + 4 + hh] = per2;
        }
    }
}

// ---------------- CSR build --------------------------------------------------
__global__ void k_csr_count(const int* __restrict__ dst) {
    int i = blockIdx.x * blockDim.x + threadIdx.x;
    if (i < EE) atomicAdd(&g_cnt[dst[i]], 1);
}

__global__ __launch_bounds__(1024) void k_scanA() {
    __shared__ int sh[1024];
    int t = threadIdx.x, idx = blockIdx.x * 1024 + t;
    int v = (idx < NN) ? g_cnt[idx] : 0;
    sh[t] = v;
    __syncthreads();
    for (int off = 1; off < 1024; off <<= 1) {
        int u = (t >= off) ? sh[t - off] : 0;
        __syncthreads();
        sh[t] += u;
        __syncthreads();
    }
    if (idx < NN) g_off[idx] = sh[t] - v;
    if (t == 1023) g_bsum2[blockIdx.x] = sh[t];
}

__global__ void k_scanB() {
    __shared__ int sh[64];
    int t = threadIdx.x;
    int v = (t < 49) ? g_bsum2[t] : 0;
    sh[t] = v;
    __syncthreads();
    for (int off = 1; off < 64; off <<= 1) {
        int u = (t >= off) ? sh[t - off] : 0;
        __syncthreads();
        sh[t] += u;
        __syncthreads();
    }
    g_bsum2[t] = sh[t] - v;
}

__global__ __launch_bounds__(1024) void k_scanC() {
    int idx = blockIdx.x * 1024 + threadIdx.x;
    if (idx < NN) {
        int o = g_off[idx] + g_bsum2[blockIdx.x];
        g_off[idx] = o;
        g_cur[idx] = o;
    }
}

__global__ void k_fill(const int* __restrict__ src, const int* __restrict__ dst) {
    int i = blockIdx.x * blockDim.x + threadIdx.x;
    if (i >= EE) return;
    int d = dst[i];
    int pos = atomicAdd(&g_cur[d], 1);
    g_eid[pos] = i;
    g_esrc[pos] = src[i];
}

// ---------------- K5: fused softmax + attn + edge-MLP + message gather -------
// one warp per node (R6 structure); forced 6 blocks/SM for occupancy
__global__ __launch_bounds__(256, 6) void k_node_all(
    const float* __restrict__ aw1, const float* __restrict__ ab1,
    const float* __restrict__ aw2, const float* __restrict__ ab2,
    float* __restrict__ attn, float* __restrict__ hout) {
    __shared__ float s_aw1[64], s_aw2[64], s_ab1[8], s_ab2[8];
    __shared__ int   s_src[8][CAP];
    __shared__ int   s_eid[8][CAP];
    __shared__ float s_a[8][CAP][8];
    __shared__ float s_zi[8][8];
    int tid = threadIdx.x;
    if (tid < 64) { s_aw1[tid] = aw1[tid]; s_aw2[tid] = aw2[tid]; }
    if (tid < 8)  { s_ab1[tid] = ab1[tid]; s_ab2[tid] = ab2[tid]; }
    __syncthreads();
    int w = tid >> 5, lane = tid & 31;
    int n = blockIdx.x * 8 + w;
    if (n >= NN) return;
    int off = g_off[n], deg = g_cnt[n];

    for (int k = lane; k < deg && k < CAP; k += 32) {
        s_src[w][k] = g_esrc[off + k];
        s_eid[w][k] = g_eid[off + k];
    }
    __syncwarp();

    int j = lane >> 3, h = lane & 7, base = lane & 24;
    int quad = lane & ~3;
    float er_h = g_er[(size_t)n * 8 + h];
    float invz;

    if (deg <= CAP) {
        float z = 0.f;
        int k = j;
        for (; k + 12 < deg; k += 16) {
            int s0 = s_src[w][k],      s1 = s_src[w][k + 4];
            int s2 = s_src[w][k + 8],  s3 = s_src[w][k + 12];
            float e0 = g_el[(size_t)s0 * 8 + h] + er_h;
            float e1 = g_el[(size_t)s1 * 8 + h] + er_h;
            float e2 = g_el[(size_t)s2 * 8 + h] + er_h;
            float e3 = g_el[(size_t)s3 * 8 + h] + er_h;
            e0 = (e0 > 0.f) ? e0 : 0.2f * e0;
            e1 = (e1 > 0.f) ? e1 : 0.2f * e1;
            e2 = (e2 > 0.f) ? e2 : 0.2f * e2;
            e3 = (e3 > 0.f) ? e3 : 0.2f * e3;
            float x0 = __expf(e0), x1 = __expf(e1), x2 = __expf(e2), x3 = __expf(e3);
            s_a[w][k][h] = x0;      s_a[w][k + 4][h] = x1;
            s_a[w][k + 8][h] = x2;  s_a[w][k + 12][h] = x3;
            z += (x0 + x1) + (x2 + x3);
        }
        for (; k < deg; k += 4) {
            int s = s_src[w][k];
            float e = g_el[(size_t)s * 8 + h] + er_h;
            e = (e > 0.f) ? e : 0.2f * e;
            float ex = __expf(e);
            s_a[w][k][h] = ex;
            z += ex;
        }
        z += __shfl_xor_sync(0xFFFFFFFF, z, 8);
        z += __shfl_xor_sync(0xFFFFFFFF, z, 16);
        invz = 1.0f / z;
        if (lane < 8) s_zi[w][lane] = invz;
        __syncwarp();

        float vd = 0.f;
        for (int kb = 0; kb < deg; kb += 4) {
            int kk2 = kb + j;
            bool act = (kk2 < deg);
            int s = 0;
            float a = 0.f;
            if (act) {
                s = s_src[w][kk2];
                a = s_a[w][kk2][h] * invz;
                attn[(size_t)s_eid[w][kk2] * 8 + h] = a;
            }
            float t = s_ab1[h];
#pragma unroll
            for (int kk = 0; kk < 8; kk++)
                t = fmaf(__shfl_sync(0xFFFFFFFF, a, base + kk), s_aw1[h * 8 + kk], t);
            float hid = fmaxf(t, 0.f);
            float t2 = s_ab2[h];
#pragma unroll
            for (int kk = 0; kk < 8; kk++)
                t2 = fmaf(__shfl_sync(0xFFFFFFFF, hid, base + kk), s_aw2[h * 8 + kk], t2);
            float val = 1.0f - t2;
            float v0 = __shfl_sync(0xFFFFFFFF, val, quad + 0);
            float v1 = __shfl_sync(0xFFFFFFFF, val, quad + 1);
            float v2 = __shfl_sync(0xFFFFFFFF, val, quad + 2);
            float v3 = __shfl_sync(0xFFFFFFFF, val, quad + 3);
            if (act) {
                if ((h & 3) == 0)
                    red_add_v4(g_sumw + (size_t)s * 8 + (h & 4), v0, v1, v2, v3);
                vd += val;
            }
        }
        vd += __shfl_xor_sync(0xFFFFFFFF, vd, 8);
        vd += __shfl_xor_sync(0xFFFFFFFF, vd, 16);
        if (lane < 8) atomicAdd(&g_sumw[(size_t)n * 8 + lane], vd);
        __syncwarp();

        int c = lane * 4, hsel = lane >> 2;
        float zi_h = s_zi[w][hsel];
        float a0 = 0.f, a1 = 0.f, a2 = 0.f, a3 = 0.f;
        int kk3 = 0;
        for (; kk3 + 8 <= deg; kk3 += 8) {
            int ss[8]; float av[8];
#pragma unroll
            for (int q = 0; q < 8; q++) {
                ss[q] = s_src[w][kk3 + q];
                av[q] = s_a[w][kk3 + q][hsel] * zi_h;
            }
            float4 ff[8];
#pragma unroll
            for (int q = 0; q < 8; q++)
                ff[q] = *(const float4*)(g_feat + (size_t)ss[q] * 128 + c);
#pragma unroll
            for (int q = 0; q < 8; q++) {
                a0 = fmaf(ff[q].x, av[q], a0); a1 = fmaf(ff[q].y, av[q], a1);
                a2 = fmaf(ff[q].z, av[q], a2); a3 = fmaf(ff[q].w, av[q], a3);
            }
        }
        for (; kk3 < deg; kk3++) {
            int s = s_src[w][kk3];
            float av = s_a[w][kk3][hsel] * zi_h;
            float4 f = *(const float4*)(g_feat + (size_t)s * 128 + c);
            a0 = fmaf(f.x, av, a0); a1 = fmaf(f.y, av, a1);
            a2 = fmaf(f.z, av, a2); a3 = fmaf(f.w, av, a3);
        }
        *(float4*)(hout + (size_t)n * 128 + c) = make_float4(a0, a1, a2, a3);
    } else {
        float z = 0.f;
        for (int k = j; k < deg; k += 4) {
            int s = (k < CAP) ? s_src[w][k] : g_esrc[off + k];
            float e = g_el[(size_t)s * 8 + h] + er_h;
            e = (e > 0.f) ? e : 0.2f * e;
            float ex = __expf(e);
            if (k < CAP) s_a[w][k][h] = ex;
            z += ex;
        }
        z += __shfl_xor_sync(0xFFFFFFFF, z, 8);
        z += __shfl_xor_sync(0xFFFFFFFF, z, 16);
        invz = 1.0f / z;
        if (lane < 8) s_zi[w][lane] = invz;
        __syncwarp();

        float vd = 0.f;
        for (int kb = 0; kb < deg; kb += 4) {
            int k = kb + j;
            bool act = (k < deg);
            int s = 0, eid = 0;
            float a = 0.f;
            if (act) {
                if (k < CAP) {
                    s = s_src[w][k]; eid = s_eid[w][k];
                    a = s_a[w][k][h] * invz;
                } else {
                    s = g_esrc[off + k]; eid = g_eid[off + k];
                    float e = g_el[(size_t)s * 8 + h] + er_h;
                    e = (e > 0.f) ? e : 0.2f * e;
                    a = __expf(e) * invz;
                }
                attn[(size_t)eid * 8 + h] = a;
            }
            float t = s_ab1[h];
#pragma unroll
            for (int kk = 0; kk < 8; kk++)
                t = fmaf(__shfl_sync(0xFFFFFFFF, a, base + kk), s_aw1[h * 8 + kk], t);
            float hid = fmaxf(t, 0.f);
            float t2 = s_ab2[h];
#pragma unroll
            for (int kk = 0; kk < 8; kk++)
                t2 = fmaf(__shfl_sync(0xFFFFFFFF, hid, base + kk), s_aw2[h * 8 + kk], t2);
            float val = 1.0f - t2;
            if (act) {
                atomicAdd(&g_sumw[(size_t)s * 8 + h], val);
                vd += val;
            }
        }
        vd += __shfl_xor_sync(0xFFFFFFFF, vd, 8);
        vd += __shfl_xor_sync(0xFFFFFFFF, vd, 16);
        if (lane < 8) atomicAdd(&g_sumw[(size_t)n * 8 + lane], vd);
        __syncwarp();

        int c = lane * 4, hsel = lane >> 2;
        float zi_h = s_zi[w][hsel];
        float a0 = 0.f, a1 = 0.f, a2 = 0.f, a3 = 0.f;
        for (int k = 0; k < deg; k++) {
            int s; float av;
            if (k < CAP) { s = s_src[w][k]; av = s_a[w][k][hsel] * zi_h; }
            else {
                s = g_esrc[off + k];
                float e = g_el[(size_t)s * 8 + hsel] + g_er[(size_t)n * 8 + hsel];
                e = (e > 0.f) ? e : 0.2f * e;
                av = __expf(e) * zi_h;
            }
            float4 f = *(const float4*)(g_feat + (size_t)s * 128 + c);
            a0 = fmaf(f.x, av, a0); a1 = fmaf(f.y, av, a1);
            a2 = fmaf(f.z, av, a2); a3 = fmaf(f.w, av, a3);
        }
        *(float4*)(hout + (size_t)n * 128 + c) = make_float4(a0, a1, a2, a3);
    }
}

// ---------------- K6: BN statistics only ------------------------------------
__global__ __launch_bounds__(256) void k_node2(
    const float* __restrict__ tw1, const float* __restrict__ tb1,
    const float* __restrict__ tw2, const float* __restrict__ tb2,
    const float* __restrict__ gb, const float* __restrict__ hout) {
    __shared__ float s_tw1[64], s_tb1[8], s_tw2[1024], s_tbg[128];
    __shared__ float s_bsum[128], s_bsq[128];
    int tid = threadIdx.x;
    if (tid < 64) s_tw1[tid] = tw1[tid];
    if (tid < 8)  s_tb1[tid] = tb1[tid];
    for (int j = tid; j < 1024; j += 256) s_tw2[j] = tw2[j];
    if (tid < 128) {
        s_tbg[tid] = tb2[tid] + gb[tid];
        s_bsum[tid] = 0.f; s_bsq[tid] = 0.f;
    }
    __syncthreads();
    int lane = tid & 31, w = tid >> 5;
    int c = lane * 4;
    float lsum[4] = {0, 0, 0, 0}, lsq[4] = {0, 0, 0, 0};
    for (int n = blockIdx.x * 8 + w; n < NN; n += gridDim.x * 8) {
        float4 sw0 = *(const float4*)(g_sumw + (size_t)n * 8);
        float4 sw1 = *(const float4*)(g_sumw + (size_t)n * 8 + 4);
        float swv[8] = {sw0.x, sw0.y, sw0.z, sw0.w, sw1.x, sw1.y, sw1.z, sw1.w};
        float hid[8];
#pragma unroll
        for (int o = 0; o < 8; o++) {
            float t = s_tb1[o];
#pragma unroll
            for (int k = 0; k < 8; k++) t = fmaf(swv[k], s_tw1[o * 8 + k], t);
            hid[o] = fmaxf(t, 0.f);
        }
        float4 acc = *(const float4*)(hout + (size_t)n * 128 + c);
        float av[4] = {acc.x, acc.y, acc.z, acc.w};
#pragma unroll
        for (int j = 0; j < 4; j++) {
            float t = s_tbg[c + j];
#pragma unroll
            for (int k = 0; k < 8; k++) t = fmaf(hid[k], s_tw2[(c + j) * 8 + k], t);
            float ov = av[j] + t;
            lsum[j] += ov;
            lsq[j]  += ov * ov;
        }
    }
#pragma unroll
    for (int j = 0; j < 4; j++) {
        atomicAdd(&s_bsum[c + j], lsum[j]);
        atomicAdd(&s_bsq[c + j], lsq[j]);
    }
    __syncthreads();
    if (tid < 128) {
        atomicAdd(&g_ssum[tid], s_bsum[tid]);
        atomicAdd(&g_ssq[tid], s_bsq[tid]);
    }
}

// ---------------- K7: e_emb recompute + batchnorm + elu + residual -----------
__global__ __launch_bounds__(256) void k_final(
    const float* __restrict__ hin,
    const float* __restrict__ gamma, const float* __restrict__ beta,
    const float* __restrict__ tw1, const float* __restrict__ tb1,
    const float* __restrict__ tw2, const float* __restrict__ tb2,
    const float* __restrict__ gb, float* __restrict__ out) {
    __shared__ float s_tw1[64], s_tb1[8], s_tw2[1024], s_tbg[128];
    __shared__ float s_scale[128], s_shift[128];
    int tid = threadIdx.x;
    if (tid < 64) s_tw1[tid] = tw1[tid];
    if (tid < 8)  s_tb1[tid] = tb1[tid];
    for (int j = tid; j < 1024; j += 256) s_tw2[j] = tw2[j];
    if (tid < 128) {
        s_tbg[tid] = tb2[tid] + gb[tid];
        const float invN = 1.0f / (float)NN;
        float mu = g_ssum[tid] * invN;
        float var = g_ssq[tid] * invN - mu * mu;
        float sc = gamma[tid] * rsqrtf(var + 1e-5f);
        s_scale[tid] = sc;
        s_shift[tid] = beta[tid] - mu * sc;
    }
    __syncthreads();
    int lane = tid & 31, w = tid >> 5;
    int c = lane * 4;
    for (int n = blockIdx.x * 8 + w; n < NN; n += gridDim.x * 8) {
        float4 sw0 = *(const float4*)(g_sumw + (size_t)n * 8);
        float4 sw1 = *(const float4*)(g_sumw + (size_t)n * 8 + 4);
        float swv[8] = {sw0.x, sw0.y, sw0.z, sw0.w, sw1.x, sw1.y, sw1.z, sw1.w};
        float hid[8];
#pragma unroll
        for (int o = 0; o < 8; o++) {
            float t = s_tb1[o];
#pragma unroll
            for (int k = 0; k < 8; k++) t = fmaf(swv[k], s_tw1[o * 8 + k], t);
            hid[o] = fmaxf(t, 0.f);
        }
        float4 acc = *(const float4*)(out + (size_t)n * 128 + c);
        float4 hv  = *(const float4*)(hin + (size_t)n * 128 + c);
        float av[4] = {acc.x, acc.y, acc.z, acc.w};
        float hvv[4] = {hv.x, hv.y, hv.z, hv.w};
        float r[4];
#pragma unroll
        for (int j = 0; j < 4; j++) {
            float t = s_tbg[c + j];
#pragma unroll
            for (int k = 0; k < 8; k++) t = fmaf(hid[k], s_tw2[(c + j) * 8 + k], t);
            float x = av[j] + t;
            float y = x * s_scale[c + j] + s_shift[c + j];
            y = (y > 0.f) ? y : expm1f(y);
            r[j] = hvv[j] + y;
        }
        *(float4*)(out + (size_t)n * 128 + c) = make_float4(r[0], r[1], r[2], r[3]);
    }
}

// ---------------- launcher ----------------------------------------------------
extern "C" void kernel_launch(void* const* d_in, const int* in_sizes, int n_in,
                              void* d_out, int out_size) {
    const float* h        = (const float*)d_in[0];
    const int*   edge_src = (const int*)d_in[1];
    const int*   edge_dst = (const int*)d_in[2];
    const float* fc_w     = (const float*)d_in[4];
    const float* attn_l   = (const float*)d_in[5];
    const float* attn_r   = (const float*)d_in[6];
    const float* gat_bias = (const float*)d_in[7];
    const float* aw1      = (const float*)d_in[8];
    const float* ab1      = (const float*)d_in[9];
    const float* aw2      = (const float*)d_in[10];
    const float* ab2      = (const float*)d_in[11];
    const float* tw1      = (const float*)d_in[12];
    const float* tb1      = (const float*)d_in[13];
    const float* tw2      = (const float*)d_in[14];
    const float* tb2      = (const float*)d_in[15];
    const float* bn_gamma = (const float*)d_in[16];
    const float* bn_beta  = (const float*)d_in[17];

    float* out  = (float*)d_out;
    float* hout = out;                              // [NN*HD]
    float* attn = out + (size_t)NN * HD;            // [EE*HH]

    const int NB = (NN + 1023) / 1024;              // 49

    k_init<<<512, 256>>>(out);
    cudaEventRecord(g_ev0, 0);
    cudaStreamWaitEvent(g_s2, g_ev0, 0);

    k_csr_count<<<(EE + 255) / 256, 256, 0, g_s2>>>(edge_dst);
    k_scanA<<<NB, 1024, 0, g_s2>>>();
    k_scanB<<<1, 64, 0, g_s2>>>();
    k_scanC<<<NB, 1024, 0, g_s2>>>();
    k_fill<<<(EE + 255) / 256, 256, 0, g_s2>>>(edge_src, edge_dst);
    cudaEventRecord(g_ev1, g_s2);

    k_gemm<<<(NN + 127) / 128, 256>>>(h, fc_w, attn_l, attn_r);

    cudaStreamWaitEvent(0, g_ev1, 0);
    k_node_all<<<(NN + 7) / 8, 256>>>(aw1, ab1, aw2, ab2, attn, hout);
    k_node2<<<296, 256>>>(tw1, tb1, tw2, tb2, gat_bias, hout);
    k_final<<<296, 256>>>(h, bn_gamma, bn_beta, tw1, tb1, tw2, tb2, gat_bias, out);
}